// round 13
// baseline (speedup 1.0000x reference)
#include <cuda_runtime.h>
#include <cuda_fp16.h>
#include <math.h>
#include <stdint.h>

#define DIMC 768
#define HEADS 12
#define HID 3072
#define BATCH 8
#define FRAMES 16
#define NTOK 196
#define BT (BATCH*FRAMES)        // 128
#define TOKENS (BT*NTOK)         // 25088
#define EDIM 64
#define M_JOINT (FRAMES*NTOK)    // 3136
#define QKVD (3*DIMC)            // 2304
#define KVCH 8                   // kv split-K chunks
#define KVBLK 98                 // 3136 / 32 row-blocks

// ---------------- scratch (static device globals; no allocation) -------------
__device__ __align__(256) __half g_xn  [(size_t)TOKENS*DIMC];
__device__ __align__(256) __half g_qkvh[(size_t)TOKENS*QKVD];
__device__ __align__(256) __half g_attn[(size_t)TOKENS*DIMC];
__device__ __align__(256) float  g_x2  [(size_t)TOKENS*DIMC];
__device__ __align__(256) __half g_hdnh[(size_t)TOKENS*HID];
__device__ __align__(256) __half g_hdn2[(size_t)TOKENS*HID];
__device__ __align__(256) float  g_kv  [96*4096];
__device__ __align__(256) float  g_ksum[96*64];
__device__ __align__(256) float  g_kvp [KVCH*96*4096];
__device__ __align__(256) float  g_ksump[KVCH*96*64];
__device__ __align__(256) __half g_wh  [7077888];

#define WR_QKV  0
#define WR_PROJ 1769472
#define WR_FC1  2359296
#define WR_FC2  4718592

// segment sizes in float4 units
#define F4_QKV  442368
#define F4_PROJ 147456
#define F4_FC1  589824
#define F4_FC2  589824
#define F4_TOT  (F4_QKV + F4_PROJ + F4_FC1 + F4_FC2)   // 1769472

// ---------------- helpers ----------------------------------------------------
__device__ __forceinline__ uint32_t smem_u32(const void* p) {
    uint32_t a;
    asm("{ .reg .u64 t; cvta.to.shared.u64 t, %1; cvt.u32.u64 %0, t; }"
        : "=r"(a) : "l"(p));
    return a;
}
#define CPA16(d,s)  asm volatile("cp.async.cg.shared.global [%0], [%1], 16;" :: "r"(d), "l"(s))
#define CP_COMMIT() asm volatile("cp.async.commit_group;" ::: "memory")

#define MMA16816(c, a, b) \
    asm volatile("mma.sync.aligned.m16n8k16.row.col.f32.f16.f16.f32 " \
        "{%0,%1,%2,%3}, {%4,%5,%6,%7}, {%8,%9}, {%0,%1,%2,%3};" \
        : "+f"((c)[0]), "+f"((c)[1]), "+f"((c)[2]), "+f"((c)[3]) \
        : "r"((a)[0]), "r"((a)[1]), "r"((a)[2]), "r"((a)[3]), \
          "r"((b)[0]), "r"((b)[1]))

// ---------------- HGEMM: C[M,N] = A[M,K] @ B[N,K]^T (+bias)(+resid) ----------
// block 128x256, K-slab 64, double-buffered cp.async, 8 warps x (64x64).
// Scalar LDS.32 fragment loads (conflict-free with PITCH=72). Reg-rich
// 1-CTA/SM schedule — measured fastest (r9/r11 alternatives both lost).
#define PITCH 72
#define A_ST (128*PITCH)
#define B_ST (256*PITCH)
#define STG_H (A_ST + B_ST)
#define HSMEM (2*STG_H*2)                // 110592 bytes

__global__ __launch_bounds__(256) void hgemm(
    const __half* __restrict__ A, const __half* __restrict__ B,
    const float* __restrict__ bias, const float* __restrict__ resid,
    float* __restrict__ C, __half* __restrict__ Ch, int M, int N, int K)
{
    extern __shared__ __half sh[];
    const int t = threadIdx.x, lane = t & 31, wid = t >> 5;
    const int blockM = blockIdx.y * 128, blockN = blockIdx.x * 256;
    const int wm = (wid & 1) * 64;
    const int wn = (wid >> 1) * 64;
    const int S = K >> 6;

    float acc[4][8][4];
    #pragma unroll
    for (int i = 0; i < 4; i++)
        #pragma unroll
        for (int j = 0; j < 8; j++)
            #pragma unroll
            for (int q = 0; q < 4; q++) acc[i][j][q] = 0.f;

#define HPRE(stg, k0) do { \
        __half* _sa = sh + (stg) * STG_H; \
        __half* _sb = _sa + A_ST; \
        _Pragma("unroll") \
        for (int _i = 0; _i < 4; _i++) { \
            int _ci = t + _i * 256; \
            int _r = _ci >> 3, _ch = _ci & 7; \
            CPA16(smem_u32(_sa + _r * PITCH + _ch * 8), \
                  A + (size_t)(blockM + _r) * K + (k0) + _ch * 8); \
        } \
        _Pragma("unroll") \
        for (int _i = 0; _i < 8; _i++) { \
            int _ci = t + _i * 256; \
            int _r = _ci >> 3, _ch = _ci & 7; \
            CPA16(smem_u32(_sb + _r * PITCH + _ch * 8), \
                  B + (size_t)(blockN + _r) * K + (k0) + _ch * 8); \
        } } while (0)

    HPRE(0, 0); CP_COMMIT();

    for (int s = 0; s < S; s++) {
        asm volatile("cp.async.wait_group 0;" ::: "memory");
        __syncthreads();
        if (s + 1 < S) HPRE((s + 1) & 1, (s + 1) * 64);
        CP_COMMIT();

        const __half* As = sh + (s & 1) * STG_H;
        const __half* Bs = As + A_ST;

        #pragma unroll
        for (int ks = 0; ks < 4; ks++) {
            int kk = ks * 16 + 2 * (lane & 3);
            uint32_t a[4][4], b[8][2];
            #pragma unroll
            for (int mt = 0; mt < 4; mt++) {
                const __half* p = As + (wm + mt*16 + (lane >> 2)) * PITCH + kk;
                a[mt][0] = *(const uint32_t*)(p);
                a[mt][1] = *(const uint32_t*)(p + 8 * PITCH);
                a[mt][2] = *(const uint32_t*)(p + 8);
                a[mt][3] = *(const uint32_t*)(p + 8 * PITCH + 8);
            }
            #pragma unroll
            for (int nt = 0; nt < 8; nt++) {
                const __half* p = Bs + (wn + nt*8 + (lane >> 2)) * PITCH + kk;
                b[nt][0] = *(const uint32_t*)(p);
                b[nt][1] = *(const uint32_t*)(p + 8);
            }
            #pragma unroll
            for (int mt = 0; mt < 4; mt++)
                #pragma unroll
                for (int nt = 0; nt < 8; nt++)
                    MMA16816(acc[mt][nt], a[mt], b[nt]);
        }
    }

    #pragma unroll
    for (int mt = 0; mt < 4; mt++) {
        int r = blockM + wm + mt * 16 + (lane >> 2);
        #pragma unroll
        for (int nt = 0; nt < 8; nt++) {
            int c = blockN + wn + nt * 8 + 2 * (lane & 3);
            float v0 = acc[mt][nt][0], v1 = acc[mt][nt][1];
            float v2 = acc[mt][nt][2], v3 = acc[mt][nt][3];
            if (bias) {
                float b0 = bias[c], b1 = bias[c + 1];
                v0 += b0; v1 += b1; v2 += b0; v3 += b1;
            }
            size_t o0 = (size_t)r * N + c;
            size_t o1 = (size_t)(r + 8) * N + c;
            if (resid) {
                float2 r0 = *(const float2*)(resid + o0);
                float2 r1 = *(const float2*)(resid + o1);
                v0 += r0.x; v1 += r0.y; v2 += r1.x; v3 += r1.y;
            }
            if (Ch) {
                *(__half2*)(Ch + o0) = __floats2half2_rn(v0, v1);
                *(__half2*)(Ch + o1) = __floats2half2_rn(v2, v3);
            } else {
                *(float2*)(C + o0) = make_float2(v0, v1);
                *(float2*)(C + o1) = make_float2(v2, v3);
            }
        }
    }
}

// ---------------- all weights fp32 -> fp16, single kernel --------------------
__global__ __launch_bounds__(256) void f2h_all_kernel(
    const float4* __restrict__ qkv_w, const float4* __restrict__ proj_w,
    const float4* __restrict__ fc1_w, const float4* __restrict__ fc2_w,
    __half2* __restrict__ out)
{
    int i = blockIdx.x * 256 + threadIdx.x;
    if (i >= F4_TOT) return;
    float4 v;
    if (i < F4_QKV) {
        v = qkv_w[i];
    } else if (i < F4_QKV + F4_PROJ) {
        v = proj_w[i - F4_QKV];
    } else if (i < F4_QKV + F4_PROJ + F4_FC1) {
        v = fc1_w[i - (F4_QKV + F4_PROJ)];
    } else {
        v = fc2_w[i - (F4_QKV + F4_PROJ + F4_FC1)];
    }
    out[i * 2]     = __floats2half2_rn(v.x, v.y);
    out[i * 2 + 1] = __floats2half2_rn(v.z, v.w);
}

// ---------------- LayerNorm: warp per row (768) ------------------------------
__global__ __launch_bounds__(256) void ln_kernel(
    const float* __restrict__ x, const float* __restrict__ w,
    const float* __restrict__ b, __half* __restrict__ out)
{
    int warp = threadIdx.x >> 5, lane = threadIdx.x & 31;
    size_t row = (size_t)blockIdx.x * 8 + warp;
    const float* xr = x + row * DIMC;
    float4 v[6];
    float s = 0.f;
    #pragma unroll
    for (int i = 0; i < 6; i++) {
        v[i] = *(const float4*)(xr + lane * 4 + i * 128);
        s += v[i].x + v[i].y + v[i].z + v[i].w;
    }
    #pragma unroll
    for (int o = 16; o; o >>= 1) s += __shfl_xor_sync(0xffffffffu, s, o);
    float mu = s * (1.0f / DIMC);
    float sq = 0.f;
    #pragma unroll
    for (int i = 0; i < 6; i++) {
        v[i].x -= mu; v[i].y -= mu; v[i].z -= mu; v[i].w -= mu;
        sq += v[i].x*v[i].x + v[i].y*v[i].y + v[i].z*v[i].z + v[i].w*v[i].w;
    }
    #pragma unroll
    for (int o = 16; o; o >>= 1) sq += __shfl_xor_sync(0xffffffffu, sq, o);
    float rs = rsqrtf(sq * (1.0f / DIMC) + 1e-5f);
    __half2* o2 = (__half2*)(out + row * DIMC);
    #pragma unroll
    for (int i = 0; i < 6; i++) {
        int c = lane * 4 + i * 128;
        float4 ww = *(const float4*)(w + c);
        float4 bb = *(const float4*)(b + c);
        o2[c/2]     = __floats2half2_rn(v[i].x * rs * ww.x + bb.x,
                                        v[i].y * rs * ww.y + bb.y);
        o2[c/2 + 1] = __floats2half2_rn(v[i].z * rs * ww.z + bb.z,
                                        v[i].w * rs * ww.w + bb.w);
    }
}

// ---------------- kv partial: per (b,h,chunk), 32-row-block-exact ------------
// LDS.128 loads (Ks/Vs rows 16B-aligned) — 2 loads + 16 FMA per row-iter.
__global__ __launch_bounds__(256) void kv_part_kernel(
    const __half* __restrict__ qkv, float* __restrict__ kvp,
    float* __restrict__ ksump)
{
    __shared__ float Ks[32][64];
    __shared__ float Vs[32][64];
    int bh = blockIdx.x, chunk = blockIdx.y;
    int b = bh / HEADS, h = bh % HEADS;
    int t = threadIdx.x;
    int lrow = t >> 3, lcol = (t & 7) * 8;
    int ge = t >> 4, gd = t & 15;

    float acc[4][4];
    float ks[4];
    #pragma unroll
    for (int i = 0; i < 4; i++) { ks[i] = 0.f;
        #pragma unroll
        for (int j = 0; j < 4; j++) acc[i][j] = 0.f; }

    int c0 = ((chunk * KVBLK) / KVCH) * 32;
    int c1 = (((chunk + 1) * KVBLK) / KVCH) * 32;
    for (int c = c0; c < c1; c += 32) {
        int m = c + lrow;
        const __half* qh = qkv + ((size_t)(b * M_JOINT + m)) * QKVD + h * EDIM + lcol;
        uint4 kraw = *(const uint4*)(qh + DIMC);
        uint4 vraw = *(const uint4*)(qh + 2 * DIMC);
        const __half2* kp = (const __half2*)&kraw;
        const __half2* vp = (const __half2*)&vraw;
        #pragma unroll
        for (int j = 0; j < 4; j++) {
            float2 kf = __half22float2(kp[j]);
            float2 vf = __half22float2(vp[j]);
            Ks[lrow][lcol + 2*j]     = fmaxf(kf.x, 0.f) + 0.125f;
            Ks[lrow][lcol + 2*j + 1] = fmaxf(kf.y, 0.f) + 0.125f;
            Vs[lrow][lcol + 2*j]     = vf.x;
            Vs[lrow][lcol + 2*j + 1] = vf.y;
        }
        __syncthreads();
        #pragma unroll 8
        for (int mm = 0; mm < 32; mm++) {
            float4 kv4 = *(const float4*)&Ks[mm][ge * 4];
            float4 vv4 = *(const float4*)&Vs[mm][gd * 4];
            const float ka[4] = {kv4.x, kv4.y, kv4.z, kv4.w};
            const float va[4] = {vv4.x, vv4.y, vv4.z, vv4.w};
            #pragma unroll
            for (int i = 0; i < 4; i++)
                #pragma unroll
                for (int j = 0; j < 4; j++)
                    acc[i][j] = fmaf(ka[i], va[j], acc[i][j]);
            if (gd == 0) {
                #pragma unroll
                for (int i = 0; i < 4; i++) ks[i] += ka[i];
            }
        }
        __syncthreads();
    }
    size_t ob = ((size_t)chunk * 96 + bh) * 4096;
    #pragma unroll
    for (int i = 0; i < 4; i++)
        #pragma unroll
        for (int j = 0; j < 4; j++)
            kvp[ob + (ge*4+i)*64 + gd*4+j] = acc[i][j];
    if (gd == 0) {
        #pragma unroll
        for (int i = 0; i < 4; i++)
            ksump[((size_t)chunk*96 + bh)*64 + ge*4+i] = ks[i];
    }
}

__global__ __launch_bounds__(256) void kv_reduce_kernel(
    const float* __restrict__ kvp, const float* __restrict__ ksump,
    float* __restrict__ kv, float* __restrict__ ksum)
{
    int i = blockIdx.x * 256 + threadIdx.x;
    if (i < 96*4096) {
        float s = 0.f;
        #pragma unroll
        for (int c = 0; c < KVCH; c++) s += kvp[(size_t)c*96*4096 + i];
        kv[i] = s;
    } else if (i < 96*4096 + 96*64) {
        int j = i - 96*4096;
        float s = 0.f;
        #pragma unroll
        for (int c = 0; c < KVCH; c++) s += ksump[c*96*64 + j];
        ksum[j] = s;
    }
}

// ---------------- attention output: tiled 64tok x 64d GEMM per block ---------
__global__ __launch_bounds__(256) void attnout_kernel(
    const __half* __restrict__ qkv, const float* __restrict__ kv,
    const float* __restrict__ ksum, __half* __restrict__ attn)
{
    __shared__ float kvs[64*64];
    __shared__ float qs[64][65];
    __shared__ float zinv[64];
    int bh = blockIdx.x, chunk = blockIdx.y;
    int b = bh / HEADS, h = bh % HEADS;
    int t = threadIdx.x;

    const float* kvg = kv + (size_t)bh * 4096;
    #pragma unroll
    for (int i = 0; i < 16; i++) kvs[t + i*256] = kvg[t + i*256];

    int tok = t >> 2, e0 = (t & 3) * 16;
    size_t gtok = (size_t)b * M_JOINT + chunk * 64 + tok;
    const __half* qg = qkv + gtok * QKVD + h * EDIM + e0;
    const float* ksg = ksum + bh * 64 + e0;
    uint4 q1 = *(const uint4*)(qg);
    uint4 q2 = *(const uint4*)(qg + 8);
    const __half2* qp1 = (const __half2*)&q1;
    const __half2* qp2 = (const __half2*)&q2;
    float zp = 0.f;
    #pragma unroll
    for (int j = 0; j < 4; j++) {
        float2 f1 = __half22float2(qp1[j]);
        float2 f2 = __half22float2(qp2[j]);
        float a0 = fmaxf(f1.x, 0.f) + 0.125f;
        float a1 = fmaxf(f1.y, 0.f) + 0.125f;
        float a2 = fmaxf(f2.x, 0.f) + 0.125f;
        float a3 = fmaxf(f2.y, 0.f) + 0.125f;
        qs[tok][e0 + 2*j]     = a0;
        qs[tok][e0 + 2*j + 1] = a1;
        qs[tok][e0 + 8 + 2*j]     = a2;
        qs[tok][e0 + 8 + 2*j + 1] = a3;
        zp = fmaf(a0, ksg[2*j], zp);
        zp = fmaf(a1, ksg[2*j + 1], zp);
        zp = fmaf(a2, ksg[8 + 2*j], zp);
        zp = fmaf(a3, ksg[8 + 2*j + 1], zp);
    }
    zp += __shfl_xor_sync(0xffffffffu, zp, 1);
    zp += __shfl_xor_sync(0xffffffffu, zp, 2);
    if ((t & 3) == 0) zinv[tok] = 1.0f / (zp + 1e-6f);
    __syncthreads();

    int ty = t >> 4, tx = t & 15;
    float acc[4][4];
    #pragma unroll
    for (int i = 0; i < 4; i++)
        #pragma unroll
        for (int j = 0; j < 4; j++) acc[i][j] = 0.f;
    #pragma unroll 8
    for (int e = 0; e < 64; e++) {
        float4 rb4 = *(const float4*)&kvs[e*64 + tx*4];
        const float rb[4] = {rb4.x, rb4.y, rb4.z, rb4.w};
        float ra[4];
        #pragma unroll
        for (int i = 0; i < 4; i++) ra[i] = qs[ty*4 + i][e];
        #pragma unroll
        for (int i = 0; i < 4; i++)
            #pragma unroll
            for (int j = 0; j < 4; j++)
                acc[i][j] = fmaf(ra[i], rb[j], acc[i][j]);
    }
    #pragma unroll
    for (int i = 0; i < 4; i++) {
        size_t gt = (size_t)b * M_JOINT + chunk * 64 + ty*4 + i;
        float zi = zinv[ty*4 + i];
        __half2* o2 = (__half2*)(attn + gt * DIMC + h * EDIM + tx*4);
        o2[0] = __floats2half2_rn(acc[i][0]*zi, acc[i][1]*zi);
        o2[1] = __floats2half2_rn(acc[i][2]*zi, acc[i][3]*zi);
    }
}

// ---------------- depthwise 3x3 + bias + exact GELU (tiled, 128ch) -----------
#define DWSM (196*64*4 + 9*64*8 + 64*8)
__global__ __launch_bounds__(256) void dwconv_gelu_kernel(
    const __half* __restrict__ hdn, const float* __restrict__ w,
    const float* __restrict__ bias, __half* __restrict__ out)
{
    extern __shared__ char dsm[];
    __half2* tile = (__half2*)dsm;                       // [196][64]
    float2*  ws   = (float2*)(dsm + 196*64*4);           // [9][64]
    float2*  bs   = (float2*)(dsm + 196*64*4 + 9*64*8);  // [64]
    int bn = blockIdx.x, cb = blockIdx.y * 128;
    int t = threadIdx.x;
    size_t ibase = (size_t)bn * NTOK * HID + cb;

    const __half2* src = (const __half2*)(hdn);
    for (int i = 0; i < 49; i++) {
        int j = t + i * 256;
        int pos = j >> 6, c2 = j & 63;
        tile[pos*64 + c2] = src[(ibase + (size_t)pos*HID)/2 + c2];
    }
    for (int j = t; j < 576; j += 256) {
        int k = j >> 6, c2 = j & 63;
        ws[k*64 + c2] = make_float2(w[(cb + c2*2)*9 + k], w[(cb + c2*2 + 1)*9 + k]);
    }
    if (t < 64) bs[t] = make_float2(bias[cb + t*2], bias[cb + t*2 + 1]);
    __syncthreads();

    for (int i = 0; i < 49; i++) {
        int j = t + i * 256;
        int pos = j >> 6, c2 = j & 63;
        int hh = pos / 14, ww = pos % 14;
        float2 acc = bs[c2];
        #pragma unroll
        for (int dy = -1; dy <= 1; dy++) {
            int y = hh + dy;
            if (y < 0 || y >= 14) continue;
            #pragma unroll
            for (int dx = -1; dx <= 1; dx++) {
                int xx = ww + dx;
                if (xx < 0 || xx >= 14) continue;
                float2 iv = __half22float2(tile[(y*14 + xx)*64 + c2]);
                float2 wv = ws[((dy+1)*3 + dx+1)*64 + c2];
                acc.x = fmaf(iv.x, wv.x, acc.x);
                acc.y = fmaf(iv.y, wv.y, acc.y);
            }
        }
        float g0 = 0.5f * acc.x * (1.0f + erff(acc.x * 0.70710678118654752f));
        float g1 = 0.5f * acc.y * (1.0f + erff(acc.y * 0.70710678118654752f));
        ((__half2*)out)[(ibase + (size_t)pos*HID)/2 + c2] = __floats2half2_rn(g0, g1);
    }
}

// ---------------- launch ----------------------------------------------------
extern "C" void kernel_launch(void* const* d_in, const int* in_sizes, int n_in,
                              void* d_out, int out_size)
{
    const float* x      = (const float*)d_in[0];
    const float* ln1_w  = (const float*)d_in[1];
    const float* ln1_b  = (const float*)d_in[2];
    const float* qkv_w  = (const float*)d_in[3];
    const float* proj_w = (const float*)d_in[4];
    const float* proj_b = (const float*)d_in[5];
    const float* ln2_w  = (const float*)d_in[6];
    const float* ln2_b  = (const float*)d_in[7];
    const float* fc1_w  = (const float*)d_in[8];
    const float* fc1_b  = (const float*)d_in[9];
    const float* dw_w   = (const float*)d_in[10];
    const float* dw_b   = (const float*)d_in[11];
    const float* fc2_w  = (const float*)d_in[12];
    const float* fc2_b  = (const float*)d_in[13];
    float* out = (float*)d_out;

    __half *p_xn, *p_qkvh, *p_attn, *p_hdnh, *p_hdn2, *p_wh;
    float  *p_x2, *p_kv, *p_ksum, *p_kvp, *p_ksump;
    cudaGetSymbolAddress((void**)&p_xn,    g_xn);
    cudaGetSymbolAddress((void**)&p_qkvh,  g_qkvh);
    cudaGetSymbolAddress((void**)&p_attn,  g_attn);
    cudaGetSymbolAddress((void**)&p_x2,    g_x2);
    cudaGetSymbolAddress((void**)&p_hdnh,  g_hdnh);
    cudaGetSymbolAddress((void**)&p_hdn2,  g_hdn2);
    cudaGetSymbolAddress((void**)&p_kv,    g_kv);
    cudaGetSymbolAddress((void**)&p_ksum,  g_ksum);
    cudaGetSymbolAddress((void**)&p_kvp,   g_kvp);
    cudaGetSymbolAddress((void**)&p_ksump, g_ksump);
    cudaGetSymbolAddress((void**)&p_wh,    g_wh);

    cudaFuncSetAttribute(hgemm, cudaFuncAttributeMaxDynamicSharedMemorySize, HSMEM);
    cudaFuncSetAttribute(dwconv_gelu_kernel, cudaFuncAttributeMaxDynamicSharedMemorySize, DWSM);

    // 0) all weights -> fp16 in one kernel (layout matches WR_* offsets)
    f2h_all_kernel<<<(F4_TOT + 255)/256, 256>>>(
        (const float4*)qkv_w, (const float4*)proj_w,
        (const float4*)fc1_w, (const float4*)fc2_w, (__half2*)p_wh);

    // 1) LN1
    ln_kernel<<<TOKENS/8, 256>>>(x, ln1_w, ln1_b, p_xn);
    // 2) QKV GEMM -> half
    hgemm<<<dim3(QKVD/256, TOKENS/128), 256, HSMEM>>>(p_xn, p_wh + WR_QKV, nullptr, nullptr,
                                                      nullptr, p_qkvh, TOKENS, QKVD, DIMC);
    // 3) kv split + reduce
    kv_part_kernel<<<dim3(96, KVCH), 256>>>(p_qkvh, p_kvp, p_ksump);
    kv_reduce_kernel<<<(96*4096 + 96*64 + 255)/256, 256>>>(p_kvp, p_ksump, p_kv, p_ksum);
    // 4) attention output
    attnout_kernel<<<dim3(96, M_JOINT/64), 256>>>(p_qkvh, p_kv, p_ksum, p_attn);
    // 5) proj + bias + residual(x) -> x2 (fp32)
    hgemm<<<dim3(DIMC/256, TOKENS/128), 256, HSMEM>>>(p_attn, p_wh + WR_PROJ, proj_b, x,
                                                      p_x2, nullptr, TOKENS, DIMC, DIMC);
    // 6) LN2
    ln_kernel<<<TOKENS/8, 256>>>(p_x2, ln2_w, ln2_b, p_xn);
    // 7) fc1 + bias -> half
    hgemm<<<dim3(HID/256, TOKENS/128), 256, HSMEM>>>(p_xn, p_wh + WR_FC1, fc1_b, nullptr,
                                                     nullptr, p_hdnh, TOKENS, HID, DIMC);
    // 8) dwconv + bias + GELU
    dwconv_gelu_kernel<<<dim3(BT, HID/128), 256, DWSM>>>(p_hdnh, dw_w, dw_b, p_hdn2);
    // 9) fc2 + bias + residual(x2) -> out
    hgemm<<<dim3(DIMC/256, TOKENS/128), 256, HSMEM>>>(p_hdn2, p_wh + WR_FC2, fc2_b, p_x2,
                                                      out, nullptr, TOKENS, DIMC, HID);
    (void)in_sizes; (void)n_in; (void)out_size;
}

// round 14
// speedup vs baseline: 1.0434x; 1.0434x over previous
#include <cuda_runtime.h>
#include <cuda_fp16.h>
#include <math.h>
#include <stdint.h>

#define DIMC 768
#define HEADS 12
#define HID 3072
#define BATCH 8
#define FRAMES 16
#define NTOK 196
#define BT (BATCH*FRAMES)        // 128
#define TOKENS (BT*NTOK)         // 25088
#define EDIM 64
#define M_JOINT (FRAMES*NTOK)    // 3136
#define QKVD (3*DIMC)            // 2304
#define KVCH 8                   // kv split-K chunks
#define KVBLK 98                 // 3136 / 32 row-blocks

// ---------------- scratch (static device globals; no allocation) -------------
__device__ __align__(256) __half g_xn  [(size_t)TOKENS*DIMC];
__device__ __align__(256) __half g_qkvh[(size_t)TOKENS*QKVD];
__device__ __align__(256) __half g_attn[(size_t)TOKENS*DIMC];
__device__ __align__(256) float  g_x2  [(size_t)TOKENS*DIMC];
__device__ __align__(256) __half g_hdnh[(size_t)TOKENS*HID];
__device__ __align__(256) __half g_hdn2[(size_t)TOKENS*HID];
__device__ __align__(256) float  g_kv  [96*4096];
__device__ __align__(256) float  g_ksum[96*64];
__device__ __align__(256) float  g_kvp [KVCH*96*4096];
__device__ __align__(256) float  g_ksump[KVCH*96*64];
__device__ __align__(256) __half g_wh  [7077888];

#define WR_QKV  0
#define WR_PROJ 1769472
#define WR_FC1  2359296
#define WR_FC2  4718592

// segment sizes in float4 units
#define F4_QKV  442368
#define F4_PROJ 147456
#define F4_FC1  589824
#define F4_FC2  589824
#define F4_TOT  (F4_QKV + F4_PROJ + F4_FC1 + F4_FC2)   // 1769472

// ---------------- helpers ----------------------------------------------------
__device__ __forceinline__ uint32_t smem_u32(const void* p) {
    uint32_t a;
    asm("{ .reg .u64 t; cvta.to.shared.u64 t, %1; cvt.u32.u64 %0, t; }"
        : "=r"(a) : "l"(p));
    return a;
}
#define CPA16(d,s)  asm volatile("cp.async.cg.shared.global [%0], [%1], 16;" :: "r"(d), "l"(s))
#define CP_COMMIT() asm volatile("cp.async.commit_group;" ::: "memory")

#define MMA16816(c, a, b) \
    asm volatile("mma.sync.aligned.m16n8k16.row.col.f32.f16.f16.f32 " \
        "{%0,%1,%2,%3}, {%4,%5,%6,%7}, {%8,%9}, {%0,%1,%2,%3};" \
        : "+f"((c)[0]), "+f"((c)[1]), "+f"((c)[2]), "+f"((c)[3]) \
        : "r"((a)[0]), "r"((a)[1]), "r"((a)[2]), "r"((a)[3]), \
          "r"((b)[0]), "r"((b)[1]))

// ---------------- HGEMM: C[M,N] = A[M,K] @ B[N,K]^T (+bias)(+resid) ----------
// block 128x256, K-slab 64, double-buffered cp.async, 8 warps x (64x64).
// Scalar LDS.32 fragment loads (conflict-free with PITCH=72). Reg-rich
// 1-CTA/SM schedule — measured fastest (r9/r11 alternatives both lost).
#define PITCH 72
#define A_ST (128*PITCH)
#define B_ST (256*PITCH)
#define STG_H (A_ST + B_ST)
#define HSMEM (2*STG_H*2)                // 110592 bytes

__global__ __launch_bounds__(256) void hgemm(
    const __half* __restrict__ A, const __half* __restrict__ B,
    const float* __restrict__ bias, const float* __restrict__ resid,
    float* __restrict__ C, __half* __restrict__ Ch, int M, int N, int K)
{
    extern __shared__ __half sh[];
    const int t = threadIdx.x, lane = t & 31, wid = t >> 5;
    const int blockM = blockIdx.y * 128, blockN = blockIdx.x * 256;
    const int wm = (wid & 1) * 64;
    const int wn = (wid >> 1) * 64;
    const int S = K >> 6;

    float acc[4][8][4];
    #pragma unroll
    for (int i = 0; i < 4; i++)
        #pragma unroll
        for (int j = 0; j < 8; j++)
            #pragma unroll
            for (int q = 0; q < 4; q++) acc[i][j][q] = 0.f;

#define HPRE(stg, k0) do { \
        __half* _sa = sh + (stg) * STG_H; \
        __half* _sb = _sa + A_ST; \
        _Pragma("unroll") \
        for (int _i = 0; _i < 4; _i++) { \
            int _ci = t + _i * 256; \
            int _r = _ci >> 3, _ch = _ci & 7; \
            CPA16(smem_u32(_sa + _r * PITCH + _ch * 8), \
                  A + (size_t)(blockM + _r) * K + (k0) + _ch * 8); \
        } \
        _Pragma("unroll") \
        for (int _i = 0; _i < 8; _i++) { \
            int _ci = t + _i * 256; \
            int _r = _ci >> 3, _ch = _ci & 7; \
            CPA16(smem_u32(_sb + _r * PITCH + _ch * 8), \
                  B + (size_t)(blockN + _r) * K + (k0) + _ch * 8); \
        } } while (0)

    HPRE(0, 0); CP_COMMIT();

    for (int s = 0; s < S; s++) {
        asm volatile("cp.async.wait_group 0;" ::: "memory");
        __syncthreads();
        if (s + 1 < S) HPRE((s + 1) & 1, (s + 1) * 64);
        CP_COMMIT();

        const __half* As = sh + (s & 1) * STG_H;
        const __half* Bs = As + A_ST;

        #pragma unroll
        for (int ks = 0; ks < 4; ks++) {
            int kk = ks * 16 + 2 * (lane & 3);
            uint32_t a[4][4], b[8][2];
            #pragma unroll
            for (int mt = 0; mt < 4; mt++) {
                const __half* p = As + (wm + mt*16 + (lane >> 2)) * PITCH + kk;
                a[mt][0] = *(const uint32_t*)(p);
                a[mt][1] = *(const uint32_t*)(p + 8 * PITCH);
                a[mt][2] = *(const uint32_t*)(p + 8);
                a[mt][3] = *(const uint32_t*)(p + 8 * PITCH + 8);
            }
            #pragma unroll
            for (int nt = 0; nt < 8; nt++) {
                const __half* p = Bs + (wn + nt*8 + (lane >> 2)) * PITCH + kk;
                b[nt][0] = *(const uint32_t*)(p);
                b[nt][1] = *(const uint32_t*)(p + 8);
            }
            #pragma unroll
            for (int mt = 0; mt < 4; mt++)
                #pragma unroll
                for (int nt = 0; nt < 8; nt++)
                    MMA16816(acc[mt][nt], a[mt], b[nt]);
        }
    }

    #pragma unroll
    for (int mt = 0; mt < 4; mt++) {
        int r = blockM + wm + mt * 16 + (lane >> 2);
        #pragma unroll
        for (int nt = 0; nt < 8; nt++) {
            int c = blockN + wn + nt * 8 + 2 * (lane & 3);
            float v0 = acc[mt][nt][0], v1 = acc[mt][nt][1];
            float v2 = acc[mt][nt][2], v3 = acc[mt][nt][3];
            if (bias) {
                float b0 = bias[c], b1 = bias[c + 1];
                v0 += b0; v1 += b1; v2 += b0; v3 += b1;
            }
            size_t o0 = (size_t)r * N + c;
            size_t o1 = (size_t)(r + 8) * N + c;
            if (resid) {
                float2 r0 = *(const float2*)(resid + o0);
                float2 r1 = *(const float2*)(resid + o1);
                v0 += r0.x; v1 += r0.y; v2 += r1.x; v3 += r1.y;
            }
            if (Ch) {
                *(__half2*)(Ch + o0) = __floats2half2_rn(v0, v1);
                *(__half2*)(Ch + o1) = __floats2half2_rn(v2, v3);
            } else {
                *(float2*)(C + o0) = make_float2(v0, v1);
                *(float2*)(C + o1) = make_float2(v2, v3);
            }
        }
    }
}

// ---------------- all weights fp32 -> fp16, single kernel --------------------
__global__ __launch_bounds__(256) void f2h_all_kernel(
    const float4* __restrict__ qkv_w, const float4* __restrict__ proj_w,
    const float4* __restrict__ fc1_w, const float4* __restrict__ fc2_w,
    __half2* __restrict__ out)
{
    int i = blockIdx.x * 256 + threadIdx.x;
    if (i >= F4_TOT) return;
    float4 v;
    if (i < F4_QKV) {
        v = qkv_w[i];
    } else if (i < F4_QKV + F4_PROJ) {
        v = proj_w[i - F4_QKV];
    } else if (i < F4_QKV + F4_PROJ + F4_FC1) {
        v = fc1_w[i - (F4_QKV + F4_PROJ)];
    } else {
        v = fc2_w[i - (F4_QKV + F4_PROJ + F4_FC1)];
    }
    out[i * 2]     = __floats2half2_rn(v.x, v.y);
    out[i * 2 + 1] = __floats2half2_rn(v.z, v.w);
}

// ---------------- LayerNorm: warp per row (768) ------------------------------
__global__ __launch_bounds__(256) void ln_kernel(
    const float* __restrict__ x, const float* __restrict__ w,
    const float* __restrict__ b, __half* __restrict__ out)
{
    int warp = threadIdx.x >> 5, lane = threadIdx.x & 31;
    size_t row = (size_t)blockIdx.x * 8 + warp;
    const float* xr = x + row * DIMC;
    float4 v[6];
    float s = 0.f;
    #pragma unroll
    for (int i = 0; i < 6; i++) {
        v[i] = *(const float4*)(xr + lane * 4 + i * 128);
        s += v[i].x + v[i].y + v[i].z + v[i].w;
    }
    #pragma unroll
    for (int o = 16; o; o >>= 1) s += __shfl_xor_sync(0xffffffffu, s, o);
    float mu = s * (1.0f / DIMC);
    float sq = 0.f;
    #pragma unroll
    for (int i = 0; i < 6; i++) {
        v[i].x -= mu; v[i].y -= mu; v[i].z -= mu; v[i].w -= mu;
        sq += v[i].x*v[i].x + v[i].y*v[i].y + v[i].z*v[i].z + v[i].w*v[i].w;
    }
    #pragma unroll
    for (int o = 16; o; o >>= 1) sq += __shfl_xor_sync(0xffffffffu, sq, o);
    float rs = rsqrtf(sq * (1.0f / DIMC) + 1e-5f);
    __half2* o2 = (__half2*)(out + row * DIMC);
    #pragma unroll
    for (int i = 0; i < 6; i++) {
        int c = lane * 4 + i * 128;
        float4 ww = *(const float4*)(w + c);
        float4 bb = *(const float4*)(b + c);
        o2[c/2]     = __floats2half2_rn(v[i].x * rs * ww.x + bb.x,
                                        v[i].y * rs * ww.y + bb.y);
        o2[c/2 + 1] = __floats2half2_rn(v[i].z * rs * ww.z + bb.z,
                                        v[i].w * rs * ww.w + bb.w);
    }
}

// ---------------- kv partial via mma: kv[e][d] = sum_tok k_[tok][e] v[tok][d]
// Stage transposed [e|d][tok] tiles (tok-pairs as half2 -> STS.32), then
// m16n8k16 with the hgemm-proven fragment pattern. fp32 accum + fp32 ksum.
#define PT 34     // transposed tile pitch (halfs), even, 2-way-conflict banks
__global__ __launch_bounds__(256) void kv_part_kernel(
    const __half* __restrict__ qkv, float* __restrict__ kvp,
    float* __restrict__ ksump)
{
    __shared__ __half KsT[64][PT];
    __shared__ __half VsT[64][PT];
    __shared__ float ksum_sm[64];
    int bh = blockIdx.x, chunk = blockIdx.y;
    int b = bh / HEADS, h = bh % HEADS;
    int t = threadIdx.x, lane = t & 31, wid = t >> 5;
    int tokp = (t & 15) * 2;        // token pair base within slab
    int eg   = (t >> 4) * 4;        // 4 dims per thread

    if (t < 64) ksum_sm[t] = 0.f;

    const int wm = (wid & 3) * 16;  // e-tile base (M)
    const int wn = (wid >> 2) * 32; // d-tile base (N)
    float acc[4][4];
    #pragma unroll
    for (int i = 0; i < 4; i++)
        #pragma unroll
        for (int j = 0; j < 4; j++) acc[i][j] = 0.f;
    float ksl[4] = {0.f, 0.f, 0.f, 0.f};

    int c0 = ((chunk * KVBLK) / KVCH) * 32;
    int c1 = (((chunk + 1) * KVBLK) / KVCH) * 32;
    __syncthreads();

    for (int c = c0; c < c1; c += 32) {
        size_t base0 = ((size_t)(b * M_JOINT + c + tokp)) * QKVD + h * EDIM + eg;
        size_t base1 = base0 + QKVD;
        uint2 k0r = *(const uint2*)(qkv + base0 + DIMC);
        uint2 k1r = *(const uint2*)(qkv + base1 + DIMC);
        uint2 v0r = *(const uint2*)(qkv + base0 + 2*DIMC);
        uint2 v1r = *(const uint2*)(qkv + base1 + 2*DIMC);
        const __half* ka0 = (const __half*)&k0r;
        const __half* ka1 = (const __half*)&k1r;
        const __half* va0 = (const __half*)&v0r;
        const __half* va1 = (const __half*)&v1r;
        #pragma unroll
        for (int j = 0; j < 4; j++) {
            float f0 = fmaxf(__half2float(ka0[j]), 0.f) + 0.125f;
            float f1 = fmaxf(__half2float(ka1[j]), 0.f) + 0.125f;
            ksl[j] += f0 + f1;
            *(__half2*)&KsT[eg + j][tokp] = __floats2half2_rn(f0, f1);
            *(__half2*)&VsT[eg + j][tokp] = __halves2half2(va0[j], va1[j]);
        }
        __syncthreads();
        #pragma unroll
        for (int ks = 0; ks < 2; ks++) {
            int kk = ks * 16 + 2 * (lane & 3);
            int ar = wm + (lane >> 2);
            uint32_t a[4];
            a[0] = *(const uint32_t*)&KsT[ar][kk];
            a[1] = *(const uint32_t*)&KsT[ar + 8][kk];
            a[2] = *(const uint32_t*)&KsT[ar][kk + 8];
            a[3] = *(const uint32_t*)&KsT[ar + 8][kk + 8];
            #pragma unroll
            for (int nt = 0; nt < 4; nt++) {
                int br = wn + nt * 8 + (lane >> 2);
                uint32_t bf[2];
                bf[0] = *(const uint32_t*)&VsT[br][kk];
                bf[1] = *(const uint32_t*)&VsT[br][kk + 8];
                MMA16816(acc[nt], a, bf);
            }
        }
        __syncthreads();
    }

    size_t ob = ((size_t)chunk * 96 + bh) * 4096;
    int r0 = wm + (lane >> 2);
    #pragma unroll
    for (int nt = 0; nt < 4; nt++) {
        int cN = wn + nt * 8 + 2 * (lane & 3);
        *(float2*)&kvp[ob + (size_t)r0 * 64 + cN]       = make_float2(acc[nt][0], acc[nt][1]);
        *(float2*)&kvp[ob + (size_t)(r0 + 8) * 64 + cN] = make_float2(acc[nt][2], acc[nt][3]);
    }
    #pragma unroll
    for (int j = 0; j < 4; j++) atomicAdd(&ksum_sm[eg + j], ksl[j]);
    __syncthreads();
    if (t < 64)
        ksump[((size_t)chunk * 96 + bh) * 64 + t] = ksum_sm[t];
}

__global__ __launch_bounds__(256) void kv_reduce_kernel(
    const float* __restrict__ kvp, const float* __restrict__ ksump,
    float* __restrict__ kv, float* __restrict__ ksum)
{
    int i = blockIdx.x * 256 + threadIdx.x;
    if (i < 96*4096) {
        float s = 0.f;
        #pragma unroll
        for (int c = 0; c < KVCH; c++) s += kvp[(size_t)c*96*4096 + i];
        kv[i] = s;
    } else if (i < 96*4096 + 96*64) {
        int j = i - 96*4096;
        float s = 0.f;
        #pragma unroll
        for (int c = 0; c < KVCH; c++) s += ksump[c*96*64 + j];
        ksum[j] = s;
    }
}

// ---------------- attention output via mma: out = (q_ @ kv) * zinv -----------
// Per block: (bh, 64-token chunk). q staged half [tok][e], kv staged half
// [d][e] (transposed gmem reads, 32B-sector-clean). zinv stays fp32.
__global__ __launch_bounds__(256) void attnout_kernel(
    const __half* __restrict__ qkv, const float* __restrict__ kv,
    const float* __restrict__ ksum, __half* __restrict__ attn)
{
    __shared__ __half qs[64][PITCH];
    __shared__ __half kvT[64][PITCH];
    __shared__ float zinv[64];
    int bh = blockIdx.x, chunk = blockIdx.y;
    int b = bh / HEADS, h = bh % HEADS;
    int t = threadIdx.x, lane = t & 31, wid = t >> 5;

    // stage q with relu+scale (half) and z partials (fp32)
    int tok = t >> 2, e0 = (t & 3) * 16;
    size_t gtokq = (size_t)b * M_JOINT + chunk * 64 + tok;
    const __half* qg = qkv + gtokq * QKVD + h * EDIM + e0;
    const float* ksg = ksum + bh * 64 + e0;
    uint4 q1 = *(const uint4*)(qg);
    uint4 q2 = *(const uint4*)(qg + 8);
    const __half* q1h = (const __half*)&q1;
    const __half* q2h = (const __half*)&q2;
    __half hq[16];
    float zp = 0.f;
    #pragma unroll
    for (int j = 0; j < 8; j++) {
        float f = fmaxf(__half2float(q1h[j]), 0.f) + 0.125f;
        zp = fmaf(f, ksg[j], zp);
        hq[j] = __float2half_rn(f);
    }
    #pragma unroll
    for (int j = 0; j < 8; j++) {
        float f = fmaxf(__half2float(q2h[j]), 0.f) + 0.125f;
        zp = fmaf(f, ksg[8 + j], zp);
        hq[8 + j] = __float2half_rn(f);
    }
    *(uint4*)&qs[tok][e0]     = *(uint4*)&hq[0];
    *(uint4*)&qs[tok][e0 + 8] = *(uint4*)&hq[8];
    zp += __shfl_xor_sync(0xffffffffu, zp, 1);
    zp += __shfl_xor_sync(0xffffffffu, zp, 2);
    if ((t & 3) == 0) zinv[tok] = 1.0f / (zp + 1e-6f);

    // stage kv transposed -> half: thread reads kv[e0+i][d], i=0..15
    int d = t >> 2;
    const float* kvg = kv + (size_t)bh * 4096;
    __half hk[16];
    #pragma unroll
    for (int i = 0; i < 16; i++)
        hk[i] = __float2half_rn(kvg[(size_t)(e0 + i) * 64 + d]);
    *(uint4*)&kvT[d][e0]     = *(uint4*)&hk[0];
    *(uint4*)&kvT[d][e0 + 8] = *(uint4*)&hk[8];
    __syncthreads();

    // mma: 4 m-warps (16 toks each) x 2 n-warps (32 d each)
    const int wm = (wid & 3) * 16;
    const int wn = (wid >> 2) * 32;
    float acc[4][4];
    #pragma unroll
    for (int i = 0; i < 4; i++)
        #pragma unroll
        for (int j = 0; j < 4; j++) acc[i][j] = 0.f;

    #pragma unroll
    for (int ks = 0; ks < 4; ks++) {
        int kk = ks * 16 + 2 * (lane & 3);
        int ar = wm + (lane >> 2);
        uint32_t a[4];
        a[0] = *(const uint32_t*)&qs[ar][kk];
        a[1] = *(const uint32_t*)&qs[ar + 8][kk];
        a[2] = *(const uint32_t*)&qs[ar][kk + 8];
        a[3] = *(const uint32_t*)&qs[ar + 8][kk + 8];
        #pragma unroll
        for (int nt = 0; nt < 4; nt++) {
            int br = wn + nt * 8 + (lane >> 2);
            uint32_t bf[2];
            bf[0] = *(const uint32_t*)&kvT[br][kk];
            bf[1] = *(const uint32_t*)&kvT[br][kk + 8];
            MMA16816(acc[nt], a, bf);
        }
    }

    int r0 = wm + (lane >> 2);
    size_t gt0 = (size_t)b * M_JOINT + chunk * 64 + r0;
    float zi0 = zinv[r0], zi1 = zinv[r0 + 8];
    #pragma unroll
    for (int nt = 0; nt < 4; nt++) {
        int cN = wn + nt * 8 + 2 * (lane & 3);
        *(__half2*)(attn + gt0 * DIMC + h * EDIM + cN) =
            __floats2half2_rn(acc[nt][0] * zi0, acc[nt][1] * zi0);
        *(__half2*)(attn + (gt0 + 8) * DIMC + h * EDIM + cN) =
            __floats2half2_rn(acc[nt][2] * zi1, acc[nt][3] * zi1);
    }
}

// ---------------- depthwise 3x3 + bias + exact GELU (tiled, 128ch) -----------
#define DWSM (196*64*4 + 9*64*8 + 64*8)
__global__ __launch_bounds__(256) void dwconv_gelu_kernel(
    const __half* __restrict__ hdn, const float* __restrict__ w,
    const float* __restrict__ bias, __half* __restrict__ out)
{
    extern __shared__ char dsm[];
    __half2* tile = (__half2*)dsm;                       // [196][64]
    float2*  ws   = (float2*)(dsm + 196*64*4);           // [9][64]
    float2*  bs   = (float2*)(dsm + 196*64*4 + 9*64*8);  // [64]
    int bn = blockIdx.x, cb = blockIdx.y * 128;
    int t = threadIdx.x;
    size_t ibase = (size_t)bn * NTOK * HID + cb;

    const __half2* src = (const __half2*)(hdn);
    for (int i = 0; i < 49; i++) {
        int j = t + i * 256;
        int pos = j >> 6, c2 = j & 63;
        tile[pos*64 + c2] = src[(ibase + (size_t)pos*HID)/2 + c2];
    }
    for (int j = t; j < 576; j += 256) {
        int k = j >> 6, c2 = j & 63;
        ws[k*64 + c2] = make_float2(w[(cb + c2*2)*9 + k], w[(cb + c2*2 + 1)*9 + k]);
    }
    if (t < 64) bs[t] = make_float2(bias[cb + t*2], bias[cb + t*2 + 1]);
    __syncthreads();

    for (int i = 0; i < 49; i++) {
        int j = t + i * 256;
        int pos = j >> 6, c2 = j & 63;
        int hh = pos / 14, ww = pos % 14;
        float2 acc = bs[c2];
        #pragma unroll
        for (int dy = -1; dy <= 1; dy++) {
            int y = hh + dy;
            if (y < 0 || y >= 14) continue;
            #pragma unroll
            for (int dx = -1; dx <= 1; dx++) {
                int xx = ww + dx;
                if (xx < 0 || xx >= 14) continue;
                float2 iv = __half22float2(tile[(y*14 + xx)*64 + c2]);
                float2 wv = ws[((dy+1)*3 + dx+1)*64 + c2];
                acc.x = fmaf(iv.x, wv.x, acc.x);
                acc.y = fmaf(iv.y, wv.y, acc.y);
            }
        }
        float g0 = 0.5f * acc.x * (1.0f + erff(acc.x * 0.70710678118654752f));
        float g1 = 0.5f * acc.y * (1.0f + erff(acc.y * 0.70710678118654752f));
        ((__half2*)out)[(ibase + (size_t)pos*HID)/2 + c2] = __floats2half2_rn(g0, g1);
    }
}

// ---------------- launch ----------------------------------------------------
extern "C" void kernel_launch(void* const* d_in, const int* in_sizes, int n_in,
                              void* d_out, int out_size)
{
    const float* x      = (const float*)d_in[0];
    const float* ln1_w  = (const float*)d_in[1];
    const float* ln1_b  = (const float*)d_in[2];
    const float* qkv_w  = (const float*)d_in[3];
    const float* proj_w = (const float*)d_in[4];
    const float* proj_b = (const float*)d_in[5];
    const float* ln2_w  = (const float*)d_in[6];
    const float* ln2_b  = (const float*)d_in[7];
    const float* fc1_w  = (const float*)d_in[8];
    const float* fc1_b  = (const float*)d_in[9];
    const float* dw_w   = (const float*)d_in[10];
    const float* dw_b   = (const float*)d_in[11];
    const float* fc2_w  = (const float*)d_in[12];
    const float* fc2_b  = (const float*)d_in[13];
    float* out = (float*)d_out;

    __half *p_xn, *p_qkvh, *p_attn, *p_hdnh, *p_hdn2, *p_wh;
    float  *p_x2, *p_kv, *p_ksum, *p_kvp, *p_ksump;
    cudaGetSymbolAddress((void**)&p_xn,    g_xn);
    cudaGetSymbolAddress((void**)&p_qkvh,  g_qkvh);
    cudaGetSymbolAddress((void**)&p_attn,  g_attn);
    cudaGetSymbolAddress((void**)&p_x2,    g_x2);
    cudaGetSymbolAddress((void**)&p_hdnh,  g_hdnh);
    cudaGetSymbolAddress((void**)&p_hdn2,  g_hdn2);
    cudaGetSymbolAddress((void**)&p_kv,    g_kv);
    cudaGetSymbolAddress((void**)&p_ksum,  g_ksum);
    cudaGetSymbolAddress((void**)&p_kvp,   g_kvp);
    cudaGetSymbolAddress((void**)&p_ksump, g_ksump);
    cudaGetSymbolAddress((void**)&p_wh,    g_wh);

    cudaFuncSetAttribute(hgemm, cudaFuncAttributeMaxDynamicSharedMemorySize, HSMEM);
    cudaFuncSetAttribute(dwconv_gelu_kernel, cudaFuncAttributeMaxDynamicSharedMemorySize, DWSM);

    // 0) all weights -> fp16 in one kernel (layout matches WR_* offsets)
    f2h_all_kernel<<<(F4_TOT + 255)/256, 256>>>(
        (const float4*)qkv_w, (const float4*)proj_w,
        (const float4*)fc1_w, (const float4*)fc2_w, (__half2*)p_wh);

    // 1) LN1
    ln_kernel<<<TOKENS/8, 256>>>(x, ln1_w, ln1_b, p_xn);
    // 2) QKV GEMM -> half
    hgemm<<<dim3(QKVD/256, TOKENS/128), 256, HSMEM>>>(p_xn, p_wh + WR_QKV, nullptr, nullptr,
                                                      nullptr, p_qkvh, TOKENS, QKVD, DIMC);
    // 3) kv split (mma) + reduce
    kv_part_kernel<<<dim3(96, KVCH), 256>>>(p_qkvh, p_kvp, p_ksump);
    kv_reduce_kernel<<<(96*4096 + 96*64 + 255)/256, 256>>>(p_kvp, p_ksump, p_kv, p_ksum);
    // 4) attention output (mma)
    attnout_kernel<<<dim3(96, M_JOINT/64), 256>>>(p_qkvh, p_kv, p_ksum, p_attn);
    // 5) proj + bias + residual(x) -> x2 (fp32)
    hgemm<<<dim3(DIMC/256, TOKENS/128), 256, HSMEM>>>(p_attn, p_wh + WR_PROJ, proj_b, x,
                                                      p_x2, nullptr, TOKENS, DIMC, DIMC);
    // 6) LN2
    ln_kernel<<<TOKENS/8, 256>>>(p_x2, ln2_w, ln2_b, p_xn);
    // 7) fc1 + bias -> half
    hgemm<<<dim3(HID/256, TOKENS/128), 256, HSMEM>>>(p_xn, p_wh + WR_FC1, fc1_b, nullptr,
                                                     nullptr, p_hdnh, TOKENS, HID, DIMC);
    // 8) dwconv + bias + GELU
    dwconv_gelu_kernel<<<dim3(BT, HID/128), 256, DWSM>>>(p_hdnh, dw_w, dw_b, p_hdn2);
    // 9) fc2 + bias + residual(x2) -> out
    hgemm<<<dim3(DIMC/256, TOKENS/128), 256, HSMEM>>>(p_hdn2, p_wh + WR_FC2, fc2_b, p_x2,
                                                      out, nullptr, TOKENS, DIMC, HID);
    (void)in_sizes; (void)n_in; (void)out_size;
}

// round 15
// speedup vs baseline: 1.0605x; 1.0165x over previous
#include <cuda_runtime.h>
#include <cuda_fp16.h>
#include <math.h>
#include <stdint.h>

#define DIMC 768
#define HEADS 12
#define HID 3072
#define BATCH 8
#define FRAMES 16
#define NTOK 196
#define BT (BATCH*FRAMES)        // 128
#define TOKENS (BT*NTOK)         // 25088
#define EDIM 64
#define M_JOINT (FRAMES*NTOK)    // 3136
#define QKVD (3*DIMC)            // 2304
#define KVCH 8                   // kv split-K chunks
#define KVBLK 98                 // 3136 / 32 row-blocks

// ---------------- scratch (static device globals; no allocation) -------------
__device__ __align__(256) __half g_xn  [(size_t)TOKENS*DIMC];
__device__ __align__(256) __half g_qkvh[(size_t)TOKENS*QKVD];
__device__ __align__(256) __half g_attn[(size_t)TOKENS*DIMC];
__device__ __align__(256) float  g_x2  [(size_t)TOKENS*DIMC];
__device__ __align__(256) __half g_hdnh[(size_t)TOKENS*HID];
__device__ __align__(256) __half g_hdn2[(size_t)TOKENS*HID];
__device__ __align__(256) float  g_kv  [96*4096];
__device__ __align__(256) float  g_ksum[96*64];
__device__ __align__(256) float  g_kvp [KVCH*96*4096];
__device__ __align__(256) float  g_ksump[KVCH*96*64];
__device__ __align__(256) __half g_wh  [7077888];

#define WR_QKV  0
#define WR_PROJ 1769472
#define WR_FC1  2359296
#define WR_FC2  4718592

// segment sizes in float4 units
#define F4_QKV  442368
#define F4_PROJ 147456
#define F4_FC1  589824
#define F4_FC2  589824
#define F4_TOT  (F4_QKV + F4_PROJ + F4_FC1 + F4_FC2)   // 1769472

// ---------------- helpers ----------------------------------------------------
__device__ __forceinline__ uint32_t smem_u32(const void* p) {
    uint32_t a;
    asm("{ .reg .u64 t; cvta.to.shared.u64 t, %1; cvt.u32.u64 %0, t; }"
        : "=r"(a) : "l"(p));
    return a;
}
#define CPA16(d,s)  asm volatile("cp.async.cg.shared.global [%0], [%1], 16;" :: "r"(d), "l"(s))
#define CP_COMMIT() asm volatile("cp.async.commit_group;" ::: "memory")

#define MMA16816(c, a, b) \
    asm volatile("mma.sync.aligned.m16n8k16.row.col.f32.f16.f16.f32 " \
        "{%0,%1,%2,%3}, {%4,%5,%6,%7}, {%8,%9}, {%0,%1,%2,%3};" \
        : "+f"((c)[0]), "+f"((c)[1]), "+f"((c)[2]), "+f"((c)[3]) \
        : "r"((a)[0]), "r"((a)[1]), "r"((a)[2]), "r"((a)[3]), \
          "r"((b)[0]), "r"((b)[1]))

// ---------------- HGEMM: C[M,N] = A[M,K] @ B[N,K]^T (+bias)(+resid) ----------
// block 128x256, K-slab 64, double-buffered cp.async, 8 warps x (64x64).
// Scalar LDS.32 fragment loads (conflict-free with PITCH=72). Reg-rich
// 1-CTA/SM schedule — measured fastest (r9/r11 alternatives both lost).
#define PITCH 72
#define A_ST (128*PITCH)
#define B_ST (256*PITCH)
#define STG_H (A_ST + B_ST)
#define HSMEM (2*STG_H*2)                // 110592 bytes

__global__ __launch_bounds__(256) void hgemm(
    const __half* __restrict__ A, const __half* __restrict__ B,
    const float* __restrict__ bias, const float* __restrict__ resid,
    float* __restrict__ C, __half* __restrict__ Ch, int M, int N, int K)
{
    extern __shared__ __half sh[];
    const int t = threadIdx.x, lane = t & 31, wid = t >> 5;
    const int blockM = blockIdx.y * 128, blockN = blockIdx.x * 256;
    const int wm = (wid & 1) * 64;
    const int wn = (wid >> 1) * 64;
    const int S = K >> 6;

    float acc[4][8][4];
    #pragma unroll
    for (int i = 0; i < 4; i++)
        #pragma unroll
        for (int j = 0; j < 8; j++)
            #pragma unroll
            for (int q = 0; q < 4; q++) acc[i][j][q] = 0.f;

#define HPRE(stg, k0) do { \
        __half* _sa = sh + (stg) * STG_H; \
        __half* _sb = _sa + A_ST; \
        _Pragma("unroll") \
        for (int _i = 0; _i < 4; _i++) { \
            int _ci = t + _i * 256; \
            int _r = _ci >> 3, _ch = _ci & 7; \
            CPA16(smem_u32(_sa + _r * PITCH + _ch * 8), \
                  A + (size_t)(blockM + _r) * K + (k0) + _ch * 8); \
        } \
        _Pragma("unroll") \
        for (int _i = 0; _i < 8; _i++) { \
            int _ci = t + _i * 256; \
            int _r = _ci >> 3, _ch = _ci & 7; \
            CPA16(smem_u32(_sb + _r * PITCH + _ch * 8), \
                  B + (size_t)(blockN + _r) * K + (k0) + _ch * 8); \
        } } while (0)

    HPRE(0, 0); CP_COMMIT();

    for (int s = 0; s < S; s++) {
        asm volatile("cp.async.wait_group 0;" ::: "memory");
        __syncthreads();
        if (s + 1 < S) HPRE((s + 1) & 1, (s + 1) * 64);
        CP_COMMIT();

        const __half* As = sh + (s & 1) * STG_H;
        const __half* Bs = As + A_ST;

        #pragma unroll
        for (int ks = 0; ks < 4; ks++) {
            int kk = ks * 16 + 2 * (lane & 3);
            uint32_t a[4][4], b[8][2];
            #pragma unroll
            for (int mt = 0; mt < 4; mt++) {
                const __half* p = As + (wm + mt*16 + (lane >> 2)) * PITCH + kk;
                a[mt][0] = *(const uint32_t*)(p);
                a[mt][1] = *(const uint32_t*)(p + 8 * PITCH);
                a[mt][2] = *(const uint32_t*)(p + 8);
                a[mt][3] = *(const uint32_t*)(p + 8 * PITCH + 8);
            }
            #pragma unroll
            for (int nt = 0; nt < 8; nt++) {
                const __half* p = Bs + (wn + nt*8 + (lane >> 2)) * PITCH + kk;
                b[nt][0] = *(const uint32_t*)(p);
                b[nt][1] = *(const uint32_t*)(p + 8);
            }
            #pragma unroll
            for (int mt = 0; mt < 4; mt++)
                #pragma unroll
                for (int nt = 0; nt < 8; nt++)
                    MMA16816(acc[mt][nt], a[mt], b[nt]);
        }
    }

    #pragma unroll
    for (int mt = 0; mt < 4; mt++) {
        int r = blockM + wm + mt * 16 + (lane >> 2);
        #pragma unroll
        for (int nt = 0; nt < 8; nt++) {
            int c = blockN + wn + nt * 8 + 2 * (lane & 3);
            float v0 = acc[mt][nt][0], v1 = acc[mt][nt][1];
            float v2 = acc[mt][nt][2], v3 = acc[mt][nt][3];
            if (bias) {
                float b0 = bias[c], b1 = bias[c + 1];
                v0 += b0; v1 += b1; v2 += b0; v3 += b1;
            }
            size_t o0 = (size_t)r * N + c;
            size_t o1 = (size_t)(r + 8) * N + c;
            if (resid) {
                float2 r0 = *(const float2*)(resid + o0);
                float2 r1 = *(const float2*)(resid + o1);
                v0 += r0.x; v1 += r0.y; v2 += r1.x; v3 += r1.y;
            }
            if (Ch) {
                *(__half2*)(Ch + o0) = __floats2half2_rn(v0, v1);
                *(__half2*)(Ch + o1) = __floats2half2_rn(v2, v3);
            } else {
                *(float2*)(C + o0) = make_float2(v0, v1);
                *(float2*)(C + o1) = make_float2(v2, v3);
            }
        }
    }
}

// ---------------- all weights fp32 -> fp16, single kernel --------------------
__global__ __launch_bounds__(256) void f2h_all_kernel(
    const float4* __restrict__ qkv_w, const float4* __restrict__ proj_w,
    const float4* __restrict__ fc1_w, const float4* __restrict__ fc2_w,
    __half2* __restrict__ out)
{
    int i = blockIdx.x * 256 + threadIdx.x;
    if (i >= F4_TOT) return;
    float4 v;
    if (i < F4_QKV) {
        v = qkv_w[i];
    } else if (i < F4_QKV + F4_PROJ) {
        v = proj_w[i - F4_QKV];
    } else if (i < F4_QKV + F4_PROJ + F4_FC1) {
        v = fc1_w[i - (F4_QKV + F4_PROJ)];
    } else {
        v = fc2_w[i - (F4_QKV + F4_PROJ + F4_FC1)];
    }
    out[i * 2]     = __floats2half2_rn(v.x, v.y);
    out[i * 2 + 1] = __floats2half2_rn(v.z, v.w);
}

// ---------------- LayerNorm: warp per row (768) ------------------------------
__global__ __launch_bounds__(256) void ln_kernel(
    const float* __restrict__ x, const float* __restrict__ w,
    const float* __restrict__ b, __half* __restrict__ out)
{
    int warp = threadIdx.x >> 5, lane = threadIdx.x & 31;
    size_t row = (size_t)blockIdx.x * 8 + warp;
    const float* xr = x + row * DIMC;
    float4 v[6];
    float s = 0.f;
    #pragma unroll
    for (int i = 0; i < 6; i++) {
        v[i] = *(const float4*)(xr + lane * 4 + i * 128);
        s += v[i].x + v[i].y + v[i].z + v[i].w;
    }
    #pragma unroll
    for (int o = 16; o; o >>= 1) s += __shfl_xor_sync(0xffffffffu, s, o);
    float mu = s * (1.0f / DIMC);
    float sq = 0.f;
    #pragma unroll
    for (int i = 0; i < 6; i++) {
        v[i].x -= mu; v[i].y -= mu; v[i].z -= mu; v[i].w -= mu;
        sq += v[i].x*v[i].x + v[i].y*v[i].y + v[i].z*v[i].z + v[i].w*v[i].w;
    }
    #pragma unroll
    for (int o = 16; o; o >>= 1) sq += __shfl_xor_sync(0xffffffffu, sq, o);
    float rs = rsqrtf(sq * (1.0f / DIMC) + 1e-5f);
    __half2* o2 = (__half2*)(out + row * DIMC);
    #pragma unroll
    for (int i = 0; i < 6; i++) {
        int c = lane * 4 + i * 128;
        float4 ww = *(const float4*)(w + c);
        float4 bb = *(const float4*)(b + c);
        o2[c/2]     = __floats2half2_rn(v[i].x * rs * ww.x + bb.x,
                                        v[i].y * rs * ww.y + bb.y);
        o2[c/2 + 1] = __floats2half2_rn(v[i].z * rs * ww.z + bb.z,
                                        v[i].w * rs * ww.w + bb.w);
    }
}

// ---------------- kv partial via mma, coalesced staging ----------------------
// Thread (tok = t>>3, ecol = (t&7)*8) reads one uint4 of k row + v row
// (8 threads x 16B = full 128B token row, perfectly coalesced), then
// transposes into KsT/VsT via scalar STS.16. MMA part identical to r14.
#define PT 34     // transposed tile pitch (halfs)
__global__ __launch_bounds__(256) void kv_part_kernel(
    const __half* __restrict__ qkv, float* __restrict__ kvp,
    float* __restrict__ ksump)
{
    __shared__ __half KsT[64][PT];
    __shared__ __half VsT[64][PT];
    __shared__ float ksum_sm[64];
    int bh = blockIdx.x, chunk = blockIdx.y;
    int b = bh / HEADS, h = bh % HEADS;
    int t = threadIdx.x, lane = t & 31, wid = t >> 5;
    int tok  = t >> 3;              // 0..31
    int ecol = (t & 7) * 8;         // 0..56

    if (t < 64) ksum_sm[t] = 0.f;

    const int wm = (wid & 3) * 16;  // e-tile base (M)
    const int wn = (wid >> 2) * 32; // d-tile base (N)
    float acc[4][4];
    #pragma unroll
    for (int i = 0; i < 4; i++)
        #pragma unroll
        for (int j = 0; j < 4; j++) acc[i][j] = 0.f;
    float ksl[8] = {0.f,0.f,0.f,0.f,0.f,0.f,0.f,0.f};

    int c0 = ((chunk * KVBLK) / KVCH) * 32;
    int c1 = (((chunk + 1) * KVBLK) / KVCH) * 32;
    __syncthreads();

    for (int c = c0; c < c1; c += 32) {
        size_t base = ((size_t)(b * M_JOINT + c + tok)) * QKVD + h * EDIM + ecol;
        uint4 kr = *(const uint4*)(qkv + base + DIMC);
        uint4 vr = *(const uint4*)(qkv + base + 2*DIMC);
        const __half* kh = (const __half*)&kr;
        const __half* vh = (const __half*)&vr;
        #pragma unroll
        for (int j = 0; j < 8; j++) {
            float fk = fmaxf(__half2float(kh[j]), 0.f) + 0.125f;
            ksl[j] += fk;
            KsT[ecol + j][tok] = __float2half_rn(fk);
            VsT[ecol + j][tok] = vh[j];
        }
        __syncthreads();
        #pragma unroll
        for (int ks = 0; ks < 2; ks++) {
            int kk = ks * 16 + 2 * (lane & 3);
            int ar = wm + (lane >> 2);
            uint32_t a[4];
            a[0] = *(const uint32_t*)&KsT[ar][kk];
            a[1] = *(const uint32_t*)&KsT[ar + 8][kk];
            a[2] = *(const uint32_t*)&KsT[ar][kk + 8];
            a[3] = *(const uint32_t*)&KsT[ar + 8][kk + 8];
            #pragma unroll
            for (int nt = 0; nt < 4; nt++) {
                int br = wn + nt * 8 + (lane >> 2);
                uint32_t bf[2];
                bf[0] = *(const uint32_t*)&VsT[br][kk];
                bf[1] = *(const uint32_t*)&VsT[br][kk + 8];
                MMA16816(acc[nt], a, bf);
            }
        }
        __syncthreads();
    }

    size_t ob = ((size_t)chunk * 96 + bh) * 4096;
    int r0 = wm + (lane >> 2);
    #pragma unroll
    for (int nt = 0; nt < 4; nt++) {
        int cN = wn + nt * 8 + 2 * (lane & 3);
        *(float2*)&kvp[ob + (size_t)r0 * 64 + cN]       = make_float2(acc[nt][0], acc[nt][1]);
        *(float2*)&kvp[ob + (size_t)(r0 + 8) * 64 + cN] = make_float2(acc[nt][2], acc[nt][3]);
    }
    #pragma unroll
    for (int j = 0; j < 8; j++) atomicAdd(&ksum_sm[ecol + j], ksl[j]);
    __syncthreads();
    if (t < 64)
        ksump[((size_t)chunk * 96 + bh) * 64 + t] = ksum_sm[t];
}

__global__ __launch_bounds__(256) void kv_reduce_kernel(
    const float* __restrict__ kvp, const float* __restrict__ ksump,
    float* __restrict__ kv, float* __restrict__ ksum)
{
    int i = blockIdx.x * 256 + threadIdx.x;
    if (i < 96*4096) {
        float s = 0.f;
        #pragma unroll
        for (int c = 0; c < KVCH; c++) s += kvp[(size_t)c*96*4096 + i];
        kv[i] = s;
    } else if (i < 96*4096 + 96*64) {
        int j = i - 96*4096;
        float s = 0.f;
        #pragma unroll
        for (int c = 0; c < KVCH; c++) s += ksump[c*96*64 + j];
        ksum[j] = s;
    }
}

// ---------------- attention output via mma: out = (q_ @ kv) * zinv -----------
__global__ __launch_bounds__(256) void attnout_kernel(
    const __half* __restrict__ qkv, const float* __restrict__ kv,
    const float* __restrict__ ksum, __half* __restrict__ attn)
{
    __shared__ __half qs[64][PITCH];
    __shared__ __half kvT[64][PITCH];
    __shared__ float zinv[64];
    int bh = blockIdx.x, chunk = blockIdx.y;
    int b = bh / HEADS, h = bh % HEADS;
    int t = threadIdx.x, lane = t & 31, wid = t >> 5;

    // stage q with relu+scale (half) and z partials (fp32)
    int tok = t >> 2, e0 = (t & 3) * 16;
    size_t gtokq = (size_t)b * M_JOINT + chunk * 64 + tok;
    const __half* qg = qkv + gtokq * QKVD + h * EDIM + e0;
    const float* ksg = ksum + bh * 64 + e0;
    uint4 q1 = *(const uint4*)(qg);
    uint4 q2 = *(const uint4*)(qg + 8);
    const __half* q1h = (const __half*)&q1;
    const __half* q2h = (const __half*)&q2;
    __half hq[16];
    float zp = 0.f;
    #pragma unroll
    for (int j = 0; j < 8; j++) {
        float f = fmaxf(__half2float(q1h[j]), 0.f) + 0.125f;
        zp = fmaf(f, ksg[j], zp);
        hq[j] = __float2half_rn(f);
    }
    #pragma unroll
    for (int j = 0; j < 8; j++) {
        float f = fmaxf(__half2float(q2h[j]), 0.f) + 0.125f;
        zp = fmaf(f, ksg[8 + j], zp);
        hq[8 + j] = __float2half_rn(f);
    }
    *(uint4*)&qs[tok][e0]     = *(uint4*)&hq[0];
    *(uint4*)&qs[tok][e0 + 8] = *(uint4*)&hq[8];
    zp += __shfl_xor_sync(0xffffffffu, zp, 1);
    zp += __shfl_xor_sync(0xffffffffu, zp, 2);
    if ((t & 3) == 0) zinv[tok] = 1.0f / (zp + 1e-6f);

    // stage kv transposed -> half
    int d = t >> 2;
    const float* kvg = kv + (size_t)bh * 4096;
    __half hk[16];
    #pragma unroll
    for (int i = 0; i < 16; i++)
        hk[i] = __float2half_rn(kvg[(size_t)(e0 + i) * 64 + d]);
    *(uint4*)&kvT[d][e0]     = *(uint4*)&hk[0];
    *(uint4*)&kvT[d][e0 + 8] = *(uint4*)&hk[8];
    __syncthreads();

    const int wm = (wid & 3) * 16;
    const int wn = (wid >> 2) * 32;
    float acc[4][4];
    #pragma unroll
    for (int i = 0; i < 4; i++)
        #pragma unroll
        for (int j = 0; j < 4; j++) acc[i][j] = 0.f;

    #pragma unroll
    for (int ks = 0; ks < 4; ks++) {
        int kk = ks * 16 + 2 * (lane & 3);
        int ar = wm + (lane >> 2);
        uint32_t a[4];
        a[0] = *(const uint32_t*)&qs[ar][kk];
        a[1] = *(const uint32_t*)&qs[ar + 8][kk];
        a[2] = *(const uint32_t*)&qs[ar][kk + 8];
        a[3] = *(const uint32_t*)&qs[ar + 8][kk + 8];
        #pragma unroll
        for (int nt = 0; nt < 4; nt++) {
            int br = wn + nt * 8 + (lane >> 2);
            uint32_t bf[2];
            bf[0] = *(const uint32_t*)&kvT[br][kk];
            bf[1] = *(const uint32_t*)&kvT[br][kk + 8];
            MMA16816(acc[nt], a, bf);
        }
    }

    int r0 = wm + (lane >> 2);
    size_t gt0 = (size_t)b * M_JOINT + chunk * 64 + r0;
    float zi0 = zinv[r0], zi1 = zinv[r0 + 8];
    #pragma unroll
    for (int nt = 0; nt < 4; nt++) {
        int cN = wn + nt * 8 + 2 * (lane & 3);
        *(__half2*)(attn + gt0 * DIMC + h * EDIM + cN) =
            __floats2half2_rn(acc[nt][0] * zi0, acc[nt][1] * zi0);
        *(__half2*)(attn + (gt0 + 8) * DIMC + h * EDIM + cN) =
            __floats2half2_rn(acc[nt][2] * zi1, acc[nt][3] * zi1);
    }
}

// ---------------- depthwise 3x3 + bias + exact GELU (tiled, 128ch) -----------
#define DWSM (196*64*4 + 9*64*8 + 64*8)
__global__ __launch_bounds__(256) void dwconv_gelu_kernel(
    const __half* __restrict__ hdn, const float* __restrict__ w,
    const float* __restrict__ bias, __half* __restrict__ out)
{
    extern __shared__ char dsm[];
    __half2* tile = (__half2*)dsm;                       // [196][64]
    float2*  ws   = (float2*)(dsm + 196*64*4);           // [9][64]
    float2*  bs   = (float2*)(dsm + 196*64*4 + 9*64*8);  // [64]
    int bn = blockIdx.x, cb = blockIdx.y * 128;
    int t = threadIdx.x;
    size_t ibase = (size_t)bn * NTOK * HID + cb;

    const __half2* src = (const __half2*)(hdn);
    for (int i = 0; i < 49; i++) {
        int j = t + i * 256;
        int pos = j >> 6, c2 = j & 63;
        tile[pos*64 + c2] = src[(ibase + (size_t)pos*HID)/2 + c2];
    }
    for (int j = t; j < 576; j += 256) {
        int k = j >> 6, c2 = j & 63;
        ws[k*64 + c2] = make_float2(w[(cb + c2*2)*9 + k], w[(cb + c2*2 + 1)*9 + k]);
    }
    if (t < 64) bs[t] = make_float2(bias[cb + t*2], bias[cb + t*2 + 1]);
    __syncthreads();

    for (int i = 0; i < 49; i++) {
        int j = t + i * 256;
        int pos = j >> 6, c2 = j & 63;
        int hh = pos / 14, ww = pos % 14;
        float2 acc = bs[c2];
        #pragma unroll
        for (int dy = -1; dy <= 1; dy++) {
            int y = hh + dy;
            if (y < 0 || y >= 14) continue;
            #pragma unroll
            for (int dx = -1; dx <= 1; dx++) {
                int xx = ww + dx;
                if (xx < 0 || xx >= 14) continue;
                float2 iv = __half22float2(tile[(y*14 + xx)*64 + c2]);
                float2 wv = ws[((dy+1)*3 + dx+1)*64 + c2];
                acc.x = fmaf(iv.x, wv.x, acc.x);
                acc.y = fmaf(iv.y, wv.y, acc.y);
            }
        }
        float g0 = 0.5f * acc.x * (1.0f + erff(acc.x * 0.70710678118654752f));
        float g1 = 0.5f * acc.y * (1.0f + erff(acc.y * 0.70710678118654752f));
        ((__half2*)out)[(ibase + (size_t)pos*HID)/2 + c2] = __floats2half2_rn(g0, g1);
    }
}

// ---------------- launch ----------------------------------------------------
extern "C" void kernel_launch(void* const* d_in, const int* in_sizes, int n_in,
                              void* d_out, int out_size)
{
    const float* x      = (const float*)d_in[0];
    const float* ln1_w  = (const float*)d_in[1];
    const float* ln1_b  = (const float*)d_in[2];
    const float* qkv_w  = (const float*)d_in[3];
    const float* proj_w = (const float*)d_in[4];
    const float* proj_b = (const float*)d_in[5];
    const float* ln2_w  = (const float*)d_in[6];
    const float* ln2_b  = (const float*)d_in[7];
    const float* fc1_w  = (const float*)d_in[8];
    const float* fc1_b  = (const float*)d_in[9];
    const float* dw_w   = (const float*)d_in[10];
    const float* dw_b   = (const float*)d_in[11];
    const float* fc2_w  = (const float*)d_in[12];
    const float* fc2_b  = (const float*)d_in[13];
    float* out = (float*)d_out;

    __half *p_xn, *p_qkvh, *p_attn, *p_hdnh, *p_hdn2, *p_wh;
    float  *p_x2, *p_kv, *p_ksum, *p_kvp, *p_ksump;
    cudaGetSymbolAddress((void**)&p_xn,    g_xn);
    cudaGetSymbolAddress((void**)&p_qkvh,  g_qkvh);
    cudaGetSymbolAddress((void**)&p_attn,  g_attn);
    cudaGetSymbolAddress((void**)&p_x2,    g_x2);
    cudaGetSymbolAddress((void**)&p_hdnh,  g_hdnh);
    cudaGetSymbolAddress((void**)&p_hdn2,  g_hdn2);
    cudaGetSymbolAddress((void**)&p_kv,    g_kv);
    cudaGetSymbolAddress((void**)&p_ksum,  g_ksum);
    cudaGetSymbolAddress((void**)&p_kvp,   g_kvp);
    cudaGetSymbolAddress((void**)&p_ksump, g_ksump);
    cudaGetSymbolAddress((void**)&p_wh,    g_wh);

    cudaFuncSetAttribute(hgemm, cudaFuncAttributeMaxDynamicSharedMemorySize, HSMEM);
    cudaFuncSetAttribute(dwconv_gelu_kernel, cudaFuncAttributeMaxDynamicSharedMemorySize, DWSM);

    // 0) all weights -> fp16 in one kernel (layout matches WR_* offsets)
    f2h_all_kernel<<<(F4_TOT + 255)/256, 256>>>(
        (const float4*)qkv_w, (const float4*)proj_w,
        (const float4*)fc1_w, (const float4*)fc2_w, (__half2*)p_wh);

    // 1) LN1
    ln_kernel<<<TOKENS/8, 256>>>(x, ln1_w, ln1_b, p_xn);
    // 2) QKV GEMM -> half
    hgemm<<<dim3(QKVD/256, TOKENS/128), 256, HSMEM>>>(p_xn, p_wh + WR_QKV, nullptr, nullptr,
                                                      nullptr, p_qkvh, TOKENS, QKVD, DIMC);
    // 3) kv split (mma, coalesced staging) + reduce
    kv_part_kernel<<<dim3(96, KVCH), 256>>>(p_qkvh, p_kvp, p_ksump);
    kv_reduce_kernel<<<(96*4096 + 96*64 + 255)/256, 256>>>(p_kvp, p_ksump, p_kv, p_ksum);
    // 4) attention output (mma)
    attnout_kernel<<<dim3(96, M_JOINT/64), 256>>>(p_qkvh, p_kv, p_ksum, p_attn);
    // 5) proj + bias + residual(x) -> x2 (fp32)
    hgemm<<<dim3(DIMC/256, TOKENS/128), 256, HSMEM>>>(p_attn, p_wh + WR_PROJ, proj_b, x,
                                                      p_x2, nullptr, TOKENS, DIMC, DIMC);
    // 6) LN2
    ln_kernel<<<TOKENS/8, 256>>>(p_x2, ln2_w, ln2_b, p_xn);
    // 7) fc1 + bias -> half
    hgemm<<<dim3(HID/256, TOKENS/128), 256, HSMEM>>>(p_xn, p_wh + WR_FC1, fc1_b, nullptr,
                                                     nullptr, p_hdnh, TOKENS, HID, DIMC);
    // 8) dwconv + bias + GELU
    dwconv_gelu_kernel<<<dim3(BT, HID/128), 256, DWSM>>>(p_hdnh, dw_w, dw_b, p_hdn2);
    // 9) fc2 + bias + residual(x2) -> out
    hgemm<<<dim3(DIMC/256, TOKENS/128), 256, HSMEM>>>(p_hdn2, p_wh + WR_FC2, fc2_b, p_x2,
                                                      out, nullptr, TOKENS, DIMC, HID);
    (void)in_sizes; (void)n_in; (void)out_size;
}